// round 1
// baseline (speedup 1.0000x reference)
#include <cuda_runtime.h>
#include <cstdint>

#define B_SZ 8192
#define H_SZ 8
#define K_SZ 4096
#define HD   128
#define D_SZ 1024

// Scratch (static device globals; no runtime allocation)
__device__ float g_zn[(size_t)B_SZ * D_SZ];            // normalized z     (32 MB)
__device__ float g_cbn[(size_t)H_SZ * K_SZ * HD];      // normalized cbs   (16 MB)
__device__ unsigned long long g_arg[B_SZ * H_SZ];      // packed argmax    (512 KB)

// ---------------------------------------------------------------------------
__global__ void init_arg_kernel() {
    int i = blockIdx.x * blockDim.x + threadIdx.x;
    if (i < B_SZ * H_SZ) g_arg[i] = 0ull;
}

// One warp per (b, h): load 128 floats, L2-normalize, store to g_zn.
__global__ void norm_z_kernel(const float* __restrict__ z) {
    int b    = blockIdx.x;
    int w    = threadIdx.x >> 5;     // head 0..7
    int lane = threadIdx.x & 31;
    size_t off = (size_t)b * D_SZ + (size_t)w * HD + (size_t)lane * 4;
    float4 a = *(const float4*)(z + off);
    float ss = a.x * a.x + a.y * a.y + a.z * a.z + a.w * a.w;
#pragma unroll
    for (int m = 16; m > 0; m >>= 1) ss += __shfl_xor_sync(0xffffffffu, ss, m);
    float n = sqrtf(ss);
    float d = fmaxf(n, 1e-12f);
    float4 o;
    o.x = a.x / d; o.y = a.y / d; o.z = a.z / d; o.w = a.w / d;
    *(float4*)(g_zn + off) = o;
}

// One warp per codebook row (h*K + k): L2-normalize into g_cbn.
__global__ void norm_cb_kernel(const float* __restrict__ cb) {
    int r    = blockIdx.x * 8 + (threadIdx.x >> 5);   // 0 .. H*K-1
    int lane = threadIdx.x & 31;
    size_t off = (size_t)r * HD + (size_t)lane * 4;
    float4 a = *(const float4*)(cb + off);
    float ss = a.x * a.x + a.y * a.y + a.z * a.z + a.w * a.w;
#pragma unroll
    for (int m = 16; m > 0; m >>= 1) ss += __shfl_xor_sync(0xffffffffu, ss, m);
    float n = sqrtf(ss);
    float d = fmaxf(n, 1e-12f);
    float4 o;
    o.x = a.x / d; o.y = a.y / d; o.z = a.z / d; o.w = a.w / d;
    *(float4*)(g_cbn + off) = o;
}

// order-preserving float -> uint key
__device__ __forceinline__ unsigned fkey(float f) {
    unsigned u = __float_as_uint(f);
    return (u & 0x80000000u) ? ~u : (u | 0x80000000u);
}

// ---------------------------------------------------------------------------
// Fused GEMM + distance write + argmax.
// Per block: 64 (batch rows) x 64 (codes), full K-inner = 128.
// 256 threads, each computes a 4x4 micro-tile in registers.
// SMEM tiles stored k-major (transposed) so the inner loop is 2 x LDS.128
// + 16 FFMA per k.
#define SM_STRIDE 68   // 64 + pad; k-row stride (68*4 = 272 B, 16B aligned)

__global__ void __launch_bounds__(256) gemm_kernel(float* __restrict__ dist) {
    extern __shared__ float sm[];
    float* As = sm;                      // [128][SM_STRIDE]
    float* Bs = sm + 128 * SM_STRIDE;    // [128][SM_STRIDE]

    const int bt = blockIdx.x;   // batch tile (64 rows)
    const int kt = blockIdx.y;   // code tile  (64 codes)
    const int h  = blockIdx.z;   // head
    const int tid = threadIdx.x;

    const float* Ag = g_zn  + (size_t)(bt * 64) * D_SZ + (size_t)h * HD;
    const float* Bg = g_cbn + ((size_t)h * K_SZ + (size_t)kt * 64) * HD;

    // Cooperative load + transpose: each warp loads one full 128-float row.
#pragma unroll
    for (int j = 0; j < 8; j++) {
        int f4  = tid + j * 256;
        int row = f4 >> 5;           // 0..63
        int k4  = (f4 & 31) << 2;    // 0,4,...,124
        float4 a = *(const float4*)(Ag + (size_t)row * D_SZ + k4);
        float4 b = *(const float4*)(Bg + (size_t)row * HD  + k4);
        As[(k4 + 0) * SM_STRIDE + row] = a.x;
        As[(k4 + 1) * SM_STRIDE + row] = a.y;
        As[(k4 + 2) * SM_STRIDE + row] = a.z;
        As[(k4 + 3) * SM_STRIDE + row] = a.w;
        Bs[(k4 + 0) * SM_STRIDE + row] = b.x;
        Bs[(k4 + 1) * SM_STRIDE + row] = b.y;
        Bs[(k4 + 2) * SM_STRIDE + row] = b.z;
        Bs[(k4 + 3) * SM_STRIDE + row] = b.w;
    }
    __syncthreads();

    const int tx = tid & 15;   // code dimension
    const int ty = tid >> 4;   // batch dimension

    float acc[4][4];
#pragma unroll
    for (int i = 0; i < 4; i++)
#pragma unroll
        for (int j = 0; j < 4; j++) acc[i][j] = 0.0f;

#pragma unroll 8
    for (int k = 0; k < 128; k++) {
        float4 a = *(const float4*)(As + k * SM_STRIDE + ty * 4);
        float4 b = *(const float4*)(Bs + k * SM_STRIDE + tx * 4);
        float av[4] = {a.x, a.y, a.z, a.w};
        float bv[4] = {b.x, b.y, b.z, b.w};
#pragma unroll
        for (int i = 0; i < 4; i++)
#pragma unroll
            for (int j = 0; j < 4; j++) acc[i][j] = fmaf(av[i], bv[j], acc[i][j]);
    }

    // Epilogue: distances + argmax reduction
    const int kbase = kt * 64 + tx * 4;
#pragma unroll
    for (int i = 0; i < 4; i++) {
        int b = bt * 64 + ty * 4 + i;
        float4 dv;
        dv.x = 1.0f - acc[i][0];
        dv.y = 1.0f - acc[i][1];
        dv.z = 1.0f - acc[i][2];
        dv.w = 1.0f - acc[i][3];
        *(float4*)(dist + ((size_t)b * H_SZ + h) * K_SZ + kbase) = dv;

        unsigned long long p = 0ull;
#pragma unroll
        for (int j = 0; j < 4; j++) {
            unsigned long long c =
                ((unsigned long long)fkey(acc[i][j]) << 32) |
                (unsigned)(K_SZ - 1 - (kbase + j));   // smaller k wins ties
            if (c > p) p = c;
        }
        // reduce across the 16 tx lanes sharing this ty (xor <= 8 stays inside)
#pragma unroll
        for (int m = 8; m > 0; m >>= 1) {
            unsigned long long q = __shfl_xor_sync(0xffffffffu, p, m);
            if (q > p) p = q;
        }
        if (tx == 0)
            atomicMax(&g_arg[(size_t)b * H_SZ + h], p);
    }
}

// ---------------------------------------------------------------------------
// One warp per (b, h): decode argmax, emit index (as float) + gather z_q row
// from the ORIGINAL (un-normalized) codebooks.
__global__ void finalize_kernel(const float* __restrict__ cb,
                                float* __restrict__ zq,
                                float* __restrict__ idx_out) {
    int w    = blockIdx.x * 8 + (threadIdx.x >> 5);  // 0 .. B*H-1
    int lane = threadIdx.x & 31;
    int b = w >> 3;
    int h = w & 7;
    unsigned long long v = g_arg[w];
    int k = (K_SZ - 1) - (int)(v & 0xFFFFFFFFull);
    if (lane == 0) idx_out[w] = (float)k;
    float4 c = *(const float4*)(cb + ((size_t)h * K_SZ + k) * HD + (size_t)lane * 4);
    *(float4*)(zq + (size_t)b * D_SZ + (size_t)h * HD + (size_t)lane * 4) = c;
}

// ---------------------------------------------------------------------------
extern "C" void kernel_launch(void* const* d_in, const int* in_sizes, int n_in,
                              void* d_out, int out_size) {
    const float* z  = (const float*)d_in[0];   // (B, D) fp32
    const float* cb = (const float*)d_in[1];   // (H, K, HD) fp32
    float* out = (float*)d_out;

    // Output tuple layout (flattened, concatenated in reference return order):
    //   z_q: B*D, indices: B*H, distances: B*H*K
    float* zq   = out;
    float* idxo = out + (size_t)B_SZ * D_SZ;
    float* dist = out + (size_t)B_SZ * D_SZ + (size_t)B_SZ * H_SZ;

    static const int smem_bytes = 2 * 128 * SM_STRIDE * sizeof(float);  // 69632
    cudaFuncSetAttribute(gemm_kernel,
                         cudaFuncAttributeMaxDynamicSharedMemorySize, smem_bytes);

    init_arg_kernel<<<64, 1024>>>();
    norm_z_kernel<<<B_SZ, 256>>>(z);
    norm_cb_kernel<<<H_SZ * K_SZ / 8, 256>>>(cb);

    dim3 grid(B_SZ / 64, K_SZ / 64, H_SZ);
    gemm_kernel<<<grid, 256, smem_bytes>>>(dist);

    finalize_kernel<<<B_SZ * H_SZ / 8, 256>>>(cb, zq, idxo);
}

// round 4
// speedup vs baseline: 5.2353x; 5.2353x over previous
#include <cuda_runtime.h>
#include <cuda_bf16.h>
#include <cstdint>

#define B_SZ 8192
#define H_SZ 8
#define K_SZ 4096
#define HD   128
#define D_SZ 1024

// ---------------- static device scratch (no runtime allocation) ------------
__device__ float          g_zn  [(size_t)B_SZ * D_SZ];        // 32 MB fp32 normalized z
__device__ float          g_cbn [(size_t)H_SZ * K_SZ * HD];   // 16 MB fp32 normalized cb
__device__ __nv_bfloat16  g_zn16[(size_t)B_SZ * D_SZ];        // 16 MB bf16
__device__ __nv_bfloat16  g_cbn16[(size_t)H_SZ * K_SZ * HD];  //  8 MB bf16
__device__ unsigned long long g_arg[B_SZ * H_SZ];             // packed approx argmax

// ---------------- helpers ---------------------------------------------------
__device__ __forceinline__ uint32_t smem_u32(const void* p) {
    uint32_t a;
    asm("{ .reg .u64 t; cvta.to.shared.u64 t, %1; cvt.u32.u64 %0, t; }" : "=r"(a) : "l"(p));
    return a;
}
__device__ __forceinline__ void ldm4(uint32_t* r, uint32_t addr) {
    asm volatile("ldmatrix.sync.aligned.m8n8.x4.shared.b16 {%0,%1,%2,%3}, [%4];"
                 : "=r"(r[0]), "=r"(r[1]), "=r"(r[2]), "=r"(r[3]) : "r"(addr));
}
__device__ __forceinline__ void mma16816(float* c, const uint32_t* a,
                                         uint32_t b0, uint32_t b1) {
    asm volatile(
        "mma.sync.aligned.m16n8k16.row.col.f32.bf16.bf16.f32 "
        "{%0,%1,%2,%3},{%4,%5,%6,%7},{%8,%9},{%0,%1,%2,%3};"
        : "+f"(c[0]), "+f"(c[1]), "+f"(c[2]), "+f"(c[3])
        : "r"(a[0]), "r"(a[1]), "r"(a[2]), "r"(a[3]), "r"(b0), "r"(b1));
}
// order-preserving float<->uint key
__device__ __forceinline__ unsigned fkey(float f) {
    unsigned u = __float_as_uint(f);
    return (u & 0x80000000u) ? ~u : (u | 0x80000000u);
}
__device__ __forceinline__ float kinv(unsigned k) {
    return __uint_as_float((k & 0x80000000u) ? (k & 0x7fffffffu) : ~k);
}

// ---------------- setup kernels --------------------------------------------
__global__ void init_arg_kernel() {
    int i = blockIdx.x * blockDim.x + threadIdx.x;
    if (i < B_SZ * H_SZ) g_arg[i] = 0ull;
}

__global__ void norm_z_kernel(const float* __restrict__ z) {
    int b = blockIdx.x, w = threadIdx.x >> 5, lane = threadIdx.x & 31;
    size_t off = (size_t)b * D_SZ + (size_t)w * HD + (size_t)lane * 4;
    float4 a = *(const float4*)(z + off);
    float ss = a.x*a.x + a.y*a.y + a.z*a.z + a.w*a.w;
#pragma unroll
    for (int m = 16; m > 0; m >>= 1) ss += __shfl_xor_sync(0xffffffffu, ss, m);
    float d = fmaxf(sqrtf(ss), 1e-12f);
    float4 o = {a.x/d, a.y/d, a.z/d, a.w/d};
    *(float4*)(g_zn + off) = o;
    uint2 p;
    p.x = ((unsigned)__bfloat16_as_ushort(__float2bfloat16_rn(o.y)) << 16) |
           (unsigned)__bfloat16_as_ushort(__float2bfloat16_rn(o.x));
    p.y = ((unsigned)__bfloat16_as_ushort(__float2bfloat16_rn(o.w)) << 16) |
           (unsigned)__bfloat16_as_ushort(__float2bfloat16_rn(o.z));
    *(uint2*)(g_zn16 + off) = p;
}

__global__ void norm_cb_kernel(const float* __restrict__ cb) {
    int r = blockIdx.x * 8 + (threadIdx.x >> 5), lane = threadIdx.x & 31;
    size_t off = (size_t)r * HD + (size_t)lane * 4;
    float4 a = *(const float4*)(cb + off);
    float ss = a.x*a.x + a.y*a.y + a.z*a.z + a.w*a.w;
#pragma unroll
    for (int m = 16; m > 0; m >>= 1) ss += __shfl_xor_sync(0xffffffffu, ss, m);
    float d = fmaxf(sqrtf(ss), 1e-12f);
    float4 o = {a.x/d, a.y/d, a.z/d, a.w/d};
    *(float4*)(g_cbn + off) = o;
    uint2 p;
    p.x = ((unsigned)__bfloat16_as_ushort(__float2bfloat16_rn(o.y)) << 16) |
           (unsigned)__bfloat16_as_ushort(__float2bfloat16_rn(o.x));
    p.y = ((unsigned)__bfloat16_as_ushort(__float2bfloat16_rn(o.w)) << 16) |
           (unsigned)__bfloat16_as_ushort(__float2bfloat16_rn(o.z));
    *(uint2*)(g_cbn16 + off) = p;
}

// ---------------- HMMA GEMM: sims + distances + approx argmax ---------------
// CTA 128(M batch) x 128(N codes), K=128 fully resident. 8 warps in 2x4.
// smem: A [128 rows x 272B], B [128 rows x 272B], s_arg[128] u64.
#define ROW_B   272
#define SM_A    0
#define SM_B    34816
#define SM_ARG  69632
#define SM_TOT  70656

__global__ void __launch_bounds__(256) gemm_kernel(float* __restrict__ dist) {
    extern __shared__ char smem[];
    uint32_t sbase = smem_u32(smem);
    unsigned long long* s_arg = (unsigned long long*)(smem + SM_ARG);

    const int tid = threadIdx.x, wid = tid >> 5, lane = tid & 31;
    const int bt = blockIdx.x, kt = blockIdx.y, h = blockIdx.z;
    const int warp_m = wid >> 2, warp_n = wid & 3;

    // ---- cooperative tile loads (16B chunks, 272B row stride) ----
    {
        const uint4* Ag = (const uint4*)g_zn16 + (size_t)(bt * 128) * 128 + h * 16;
#pragma unroll
        for (int it = 0; it < 8; it++) {
            int idx = it * 256 + tid;
            int row = idx >> 4, c = idx & 15;
            uint4 v = Ag[(size_t)row * 128 + c];
            *(uint4*)(smem + SM_A + row * ROW_B + c * 16) = v;
        }
        const uint4* Bg = (const uint4*)g_cbn16 +
                          ((size_t)h * K_SZ + (size_t)kt * 128) * 16;
#pragma unroll
        for (int it = 0; it < 8; it++) {
            int idx = it * 256 + tid;
            int row = idx >> 4, c = idx & 15;
            uint4 v = Bg[(size_t)row * 16 + c];
            *(uint4*)(smem + SM_B + row * ROW_B + c * 16) = v;
        }
    }
    if (tid < 128) s_arg[tid] = 0ull;
    __syncthreads();

    // ---- ldmatrix lane bases ----
    // A x4: lanes0-7 (m0-7,k0) | 8-15 (m8-15,k0) | 16-23 (m0-7,k8) | 24-31 (m8-15,k8)
    const uint32_t a_base = sbase + SM_A +
        (uint32_t)((warp_m * 64 + ((lane >> 3) & 1) * 8 + (lane & 7)) * ROW_B +
                   (lane >> 4) * 16);
    // B x4: lanes0-7 (n0-7,k0) | 8-15 (n0-7,k8) | 16-23 (n8-15,k0) | 24-31 (n8-15,k8)
    const uint32_t b_base = sbase + SM_B +
        (uint32_t)((warp_n * 32 + (lane >> 4) * 8 + (lane & 7)) * ROW_B +
                   ((lane >> 3) & 1) * 16);

    float acc[4][4][4];
#pragma unroll
    for (int mt = 0; mt < 4; mt++)
#pragma unroll
        for (int j = 0; j < 4; j++)
#pragma unroll
            for (int r = 0; r < 4; r++) acc[mt][j][r] = 0.0f;

#pragma unroll
    for (int ks = 0; ks < 8; ks++) {
        uint32_t af[4][4], bf[2][4];
#pragma unroll
        for (int mt = 0; mt < 4; mt++)
            ldm4(af[mt], a_base + mt * (16 * ROW_B) + ks * 32);
#pragma unroll
        for (int nt = 0; nt < 2; nt++)
            ldm4(bf[nt], b_base + nt * (16 * ROW_B) + ks * 32);
#pragma unroll
        for (int mt = 0; mt < 4; mt++)
#pragma unroll
            for (int j = 0; j < 4; j++)
                mma16816(acc[mt][j], af[mt],
                         bf[j >> 1][(j & 1) ? 2 : 0],
                         bf[j >> 1][(j & 1) ? 3 : 1]);
    }

    // ---- epilogue: distances + per-row argmax ----
#pragma unroll
    for (int mt = 0; mt < 4; mt++) {
        int r0  = warp_m * 64 + mt * 16 + (lane >> 2);   // CTA row (c0,c1); +8 for c2,c3
        int gb0 = bt * 128 + r0;
        int kc  = kt * 128 + warp_n * 32 + (lane & 3) * 2;
        float* p0 = dist + ((size_t)gb0 * H_SZ + h) * K_SZ + kc;
        float* p1 = p0 + (size_t)8 * H_SZ * K_SZ;
        unsigned long long best0 = 0ull, best1 = 0ull;
#pragma unroll
        for (int j = 0; j < 4; j++) {
            float c0 = acc[mt][j][0], c1 = acc[mt][j][1];
            float c2 = acc[mt][j][2], c3 = acc[mt][j][3];
            int gk = kc + j * 8;
            *(float2*)(p0 + j * 8) = make_float2(1.0f - c0, 1.0f - c1);
            *(float2*)(p1 + j * 8) = make_float2(1.0f - c2, 1.0f - c3);
            unsigned long long k0 =
                ((unsigned long long)fkey(c0) << 32) | (unsigned)(K_SZ - 1 - gk);
            unsigned long long k1 =
                ((unsigned long long)fkey(c1) << 32) | (unsigned)(K_SZ - 2 - gk);
            unsigned long long k2 =
                ((unsigned long long)fkey(c2) << 32) | (unsigned)(K_SZ - 1 - gk);
            unsigned long long k3 =
                ((unsigned long long)fkey(c3) << 32) | (unsigned)(K_SZ - 2 - gk);
            if (k1 > k0) k0 = k1;
            if (k0 > best0) best0 = k0;
            if (k3 > k2) k2 = k3;
            if (k2 > best1) best1 = k2;
        }
#pragma unroll
        for (int m = 1; m <= 2; m <<= 1) {
            unsigned long long q0 = __shfl_xor_sync(0xffffffffu, best0, m);
            unsigned long long q1 = __shfl_xor_sync(0xffffffffu, best1, m);
            if (q0 > best0) best0 = q0;
            if (q1 > best1) best1 = q1;
        }
        if ((lane & 3) == 0) {
            atomicMax(&s_arg[r0], best0);
            atomicMax(&s_arg[r0 + 8], best1);
        }
    }
    __syncthreads();
    if (tid < 128)
        atomicMax(&g_arg[(size_t)(bt * 128 + tid) * H_SZ + h], s_arg[tid]);
}

// ---------------- rescue: exact fp32 argmax + finalize ----------------------
#define MARGIN 8e-3f
__global__ void __launch_bounds__(256) rescue_kernel(const float* __restrict__ dist,
                                                     const float* __restrict__ cb,
                                                     float* __restrict__ zq,
                                                     float* __restrict__ idx_out) {
    int w = blockIdx.x * 8 + (threadIdx.x >> 5);  // (b*H + h)
    int lane = threadIdx.x & 31;
    int b = w >> 3, h = w & 7;

    float amax = kinv((unsigned)(g_arg[w] >> 32));
    float thr = amax - MARGIN;
    const float4* dd = (const float4*)(dist + (size_t)w * K_SZ);
    const float* za = g_zn + (size_t)b * D_SZ + (size_t)h * HD;

    unsigned long long best = 0ull;
#pragma unroll 4
    for (int c4 = lane; c4 < K_SZ / 4; c4 += 32) {
        float4 v = __ldg(dd + c4);
        float s4[4] = {1.0f - v.x, 1.0f - v.y, 1.0f - v.z, 1.0f - v.w};
#pragma unroll
        for (int j = 0; j < 4; j++) {
            if (s4[j] >= thr) {
                int k = c4 * 4 + j;
                const float4* cw = (const float4*)(g_cbn + ((size_t)h * K_SZ + k) * HD);
                const float4* zz = (const float4*)za;
                float s = 0.0f;
#pragma unroll
                for (int d = 0; d < 32; d++) {
                    float4 cv = __ldg(cw + d);
                    float4 zv = zz[d];
                    s = fmaf(zv.x, cv.x, s);
                    s = fmaf(zv.y, cv.y, s);
                    s = fmaf(zv.z, cv.z, s);
                    s = fmaf(zv.w, cv.w, s);
                }
                unsigned long long key =
                    ((unsigned long long)fkey(s) << 32) | (unsigned)(K_SZ - 1 - k);
                if (key > best) best = key;
            }
        }
    }
#pragma unroll
    for (int m = 16; m > 0; m >>= 1) {
        unsigned long long q = __shfl_xor_sync(0xffffffffu, best, m);
        if (q > best) best = q;
    }
    int kbest = (K_SZ - 1) - (int)(best & 0xffffffffull);
    if (lane == 0) idx_out[w] = (float)kbest;
    float4 c = *(const float4*)(cb + ((size_t)h * K_SZ + kbest) * HD + (size_t)lane * 4);
    *(float4*)(zq + (size_t)b * D_SZ + (size_t)h * HD + (size_t)lane * 4) = c;
}

// ---------------------------------------------------------------------------
extern "C" void kernel_launch(void* const* d_in, const int* in_sizes, int n_in,
                              void* d_out, int out_size) {
    const float* z  = (const float*)d_in[0];
    const float* cb = (const float*)d_in[1];
    float* out = (float*)d_out;

    float* zq   = out;
    float* idxo = out + (size_t)B_SZ * D_SZ;
    float* dist = out + (size_t)B_SZ * D_SZ + (size_t)B_SZ * H_SZ;

    cudaFuncSetAttribute(gemm_kernel,
                         cudaFuncAttributeMaxDynamicSharedMemorySize, SM_TOT);

    init_arg_kernel<<<64, 1024>>>();
    norm_z_kernel<<<B_SZ, 256>>>(z);
    norm_cb_kernel<<<H_SZ * K_SZ / 8, 256>>>(cb);

    dim3 grid(B_SZ / 128, K_SZ / 128, H_SZ);
    gemm_kernel<<<grid, 256, SM_TOT>>>(dist);

    rescue_kernel<<<B_SZ * H_SZ / 8, 256>>>(dist, cb, zq, idxo);
}

// round 5
// speedup vs baseline: 7.1752x; 1.3705x over previous
#include <cuda_runtime.h>
#include <cuda_bf16.h>
#include <cstdint>

#define B_SZ 8192
#define H_SZ 8
#define K_SZ 4096
#define HD   128
#define D_SZ 1024

// ---------------- static device scratch (no runtime allocation) ------------
__device__ float          g_zn  [(size_t)B_SZ * D_SZ];         // fp32 normalized z
__device__ float          g_cbn [(size_t)H_SZ * K_SZ * HD];    // fp32 normalized cb
__device__ __nv_bfloat16  g_zn16[(size_t)B_SZ * D_SZ];         // bf16
__device__ __nv_bfloat16  g_cbn16[(size_t)H_SZ * K_SZ * HD];   // bf16
__device__ unsigned long long g_tilemax[(size_t)B_SZ * H_SZ * 32]; // per-row per-tile best key

// ---------------- helpers ---------------------------------------------------
__device__ __forceinline__ uint32_t smem_u32(const void* p) {
    uint32_t a;
    asm("{ .reg .u64 t; cvta.to.shared.u64 t, %1; cvt.u32.u64 %0, t; }" : "=r"(a) : "l"(p));
    return a;
}
__device__ __forceinline__ void ldm4(uint32_t* r, uint32_t addr) {
    asm volatile("ldmatrix.sync.aligned.m8n8.x4.shared.b16 {%0,%1,%2,%3}, [%4];"
                 : "=r"(r[0]), "=r"(r[1]), "=r"(r[2]), "=r"(r[3]) : "r"(addr));
}
__device__ __forceinline__ void mma16816(float* c, const uint32_t* a,
                                         uint32_t b0, uint32_t b1) {
    asm volatile(
        "mma.sync.aligned.m16n8k16.row.col.f32.bf16.bf16.f32 "
        "{%0,%1,%2,%3},{%4,%5,%6,%7},{%8,%9},{%0,%1,%2,%3};"
        : "+f"(c[0]), "+f"(c[1]), "+f"(c[2]), "+f"(c[3])
        : "r"(a[0]), "r"(a[1]), "r"(a[2]), "r"(a[3]), "r"(b0), "r"(b1));
}
#define CP_ASYNC16(dst, src) \
    asm volatile("cp.async.cg.shared.global [%0], [%1], 16;" :: "r"(dst), "l"(src))
#define CP_COMMIT() asm volatile("cp.async.commit_group;" ::: "memory")
#define CP_WAIT0()  asm volatile("cp.async.wait_group 0;" ::: "memory")
#define CP_WAIT1()  asm volatile("cp.async.wait_group 1;" ::: "memory")

// order-preserving float<->uint key
__device__ __forceinline__ unsigned fkey(float f) {
    unsigned u = __float_as_uint(f);
    return (u & 0x80000000u) ? ~u : (u | 0x80000000u);
}
__device__ __forceinline__ float kinv(unsigned k) {
    return __uint_as_float((k & 0x80000000u) ? (k & 0x7fffffffu) : ~k);
}

// ---------------- setup kernels --------------------------------------------
__global__ void norm_z_kernel(const float* __restrict__ z) {
    int b = blockIdx.x, w = threadIdx.x >> 5, lane = threadIdx.x & 31;
    size_t off = (size_t)b * D_SZ + (size_t)w * HD + (size_t)lane * 4;
    float4 a = *(const float4*)(z + off);
    float ss = a.x*a.x + a.y*a.y + a.z*a.z + a.w*a.w;
#pragma unroll
    for (int m = 16; m > 0; m >>= 1) ss += __shfl_xor_sync(0xffffffffu, ss, m);
    float d = fmaxf(sqrtf(ss), 1e-12f);
    float4 o = {a.x/d, a.y/d, a.z/d, a.w/d};
    *(float4*)(g_zn + off) = o;
    uint2 p;
    p.x = ((unsigned)__bfloat16_as_ushort(__float2bfloat16_rn(o.y)) << 16) |
           (unsigned)__bfloat16_as_ushort(__float2bfloat16_rn(o.x));
    p.y = ((unsigned)__bfloat16_as_ushort(__float2bfloat16_rn(o.w)) << 16) |
           (unsigned)__bfloat16_as_ushort(__float2bfloat16_rn(o.z));
    *(uint2*)(g_zn16 + off) = p;
}

__global__ void norm_cb_kernel(const float* __restrict__ cb) {
    int r = blockIdx.x * 8 + (threadIdx.x >> 5), lane = threadIdx.x & 31;
    size_t off = (size_t)r * HD + (size_t)lane * 4;
    float4 a = *(const float4*)(cb + off);
    float ss = a.x*a.x + a.y*a.y + a.z*a.z + a.w*a.w;
#pragma unroll
    for (int m = 16; m > 0; m >>= 1) ss += __shfl_xor_sync(0xffffffffu, ss, m);
    float d = fmaxf(sqrtf(ss), 1e-12f);
    float4 o = {a.x/d, a.y/d, a.z/d, a.w/d};
    *(float4*)(g_cbn + off) = o;
    uint2 p;
    p.x = ((unsigned)__bfloat16_as_ushort(__float2bfloat16_rn(o.y)) << 16) |
           (unsigned)__bfloat16_as_ushort(__float2bfloat16_rn(o.x));
    p.y = ((unsigned)__bfloat16_as_ushort(__float2bfloat16_rn(o.w)) << 16) |
           (unsigned)__bfloat16_as_ushort(__float2bfloat16_rn(o.z));
    *(uint2*)(g_cbn16 + off) = p;
}

// ---------------- HMMA GEMM (persistent over kt, cp.async pipelined) --------
// CTA = 128 batch rows x (KT_PER_CTA x 128) codes, K=128. 8 warps 2x4,
// warp tile 64x32. A resident in regs after one load; B double-buffered.
#define ROW_B   272
#define TILE_B  34816          /* 128 rows * 272 B */
#define SM_A    0
#define SM_B    34816
#define SM_ARG  104448
#define SM_TOT  105472
#define KT_PER_CTA 16

__global__ void __launch_bounds__(256) gemm_kernel(float* __restrict__ dist) {
    extern __shared__ char smem[];
    uint32_t sbase = smem_u32(smem);
    unsigned long long* s_arg = (unsigned long long*)(smem + SM_ARG);

    const int tid = threadIdx.x, wid = tid >> 5, lane = tid & 31;
    const int bt = blockIdx.x, h = blockIdx.y, kt0 = blockIdx.z * KT_PER_CTA;
    const int warp_m = wid >> 2, warp_n = wid & 3;

    // ---- issue A tile + first B tile (group 0) ----
    const char* Ag = (const char*)(g_zn16 + (size_t)(bt * 128) * D_SZ + h * HD);
    const char* Bg = (const char*)(g_cbn16 +
                     ((size_t)h * K_SZ + (size_t)kt0 * 128) * HD);
#pragma unroll
    for (int it = 0; it < 8; it++) {
        int idx = it * 256 + tid;
        int row = idx >> 4, c = idx & 15;
        CP_ASYNC16(sbase + SM_A + row * ROW_B + c * 16,
                   Ag + (size_t)row * (D_SZ * 2) + c * 16);
    }
#pragma unroll
    for (int it = 0; it < 8; it++) {
        int idx = it * 256 + tid;
        int row = idx >> 4, c = idx & 15;
        CP_ASYNC16(sbase + SM_B + row * ROW_B + c * 16,
                   Bg + (size_t)row * 256 + c * 16);
    }
    CP_COMMIT();
    if (tid < 128) s_arg[tid] = 0ull;

    // ldmatrix lane bases (same mapping as validated R4 kernel)
    const uint32_t a_base = sbase + SM_A +
        (uint32_t)((warp_m * 64 + ((lane >> 3) & 1) * 8 + (lane & 7)) * ROW_B +
                   (lane >> 4) * 16);
    const uint32_t b_off =
        (uint32_t)((warp_n * 32 + (lane >> 4) * 8 + (lane & 7)) * ROW_B +
                   ((lane >> 3) & 1) * 16);

    uint32_t aF[4][8][4];   // A fragments cached in registers

    for (int kti = 0; kti < KT_PER_CTA; kti++) {
        const int kt = kt0 + kti;
        // prefetch next B, then wait for current
        if (kti < KT_PER_CTA - 1) {
            const char* Bn = Bg + (size_t)(kti + 1) * 128 * 256;
            uint32_t bdst = sbase + SM_B + ((kti + 1) & 1) * TILE_B;
#pragma unroll
            for (int it = 0; it < 8; it++) {
                int idx = it * 256 + tid;
                int row = idx >> 4, c = idx & 15;
                CP_ASYNC16(bdst + row * ROW_B + c * 16,
                           Bn + (size_t)row * 256 + c * 16);
            }
            CP_COMMIT();
            CP_WAIT1();
        } else {
            CP_WAIT0();
        }
        __syncthreads();

        if (kti == 0) {
#pragma unroll
            for (int mt = 0; mt < 4; mt++)
#pragma unroll
                for (int ks = 0; ks < 8; ks++)
                    ldm4(aF[mt][ks], a_base + mt * (16 * ROW_B) + ks * 32);
        }

        const uint32_t b_base = sbase + SM_B + (kti & 1) * TILE_B + b_off;

        float acc[4][4][4];
#pragma unroll
        for (int mt = 0; mt < 4; mt++)
#pragma unroll
            for (int j = 0; j < 4; j++)
#pragma unroll
                for (int r = 0; r < 4; r++) acc[mt][j][r] = 0.0f;

#pragma unroll
        for (int ks = 0; ks < 8; ks++) {
            uint32_t bf[2][4];
            ldm4(bf[0], b_base + ks * 32);
            ldm4(bf[1], b_base + 16 * ROW_B + ks * 32);
#pragma unroll
            for (int mt = 0; mt < 4; mt++)
#pragma unroll
                for (int j = 0; j < 4; j++)
                    mma16816(acc[mt][j], aF[mt][ks],
                             bf[j >> 1][(j & 1) ? 2 : 0],
                             bf[j >> 1][(j & 1) ? 3 : 1]);
        }

        // ---- epilogue: distances + per-row tile-max ----
#pragma unroll
        for (int mt = 0; mt < 4; mt++) {
            int r0  = warp_m * 64 + mt * 16 + (lane >> 2);
            int gb0 = bt * 128 + r0;
            int kc  = kt * 128 + warp_n * 32 + (lane & 3) * 2;
            float* p0 = dist + ((size_t)gb0 * H_SZ + h) * K_SZ + kc;
            float* p1 = p0 + (size_t)8 * H_SZ * K_SZ;
            unsigned long long best0 = 0ull, best1 = 0ull;
#pragma unroll
            for (int j = 0; j < 4; j++) {
                float c0 = acc[mt][j][0], c1 = acc[mt][j][1];
                float c2 = acc[mt][j][2], c3 = acc[mt][j][3];
                int gk = kc + j * 8;
                *(float2*)(p0 + j * 8) = make_float2(1.0f - c0, 1.0f - c1);
                *(float2*)(p1 + j * 8) = make_float2(1.0f - c2, 1.0f - c3);
                unsigned long long k0 =
                    ((unsigned long long)fkey(c0) << 32) | (unsigned)(K_SZ - 1 - gk);
                unsigned long long k1 =
                    ((unsigned long long)fkey(c1) << 32) | (unsigned)(K_SZ - 2 - gk);
                unsigned long long k2 =
                    ((unsigned long long)fkey(c2) << 32) | (unsigned)(K_SZ - 1 - gk);
                unsigned long long k3 =
                    ((unsigned long long)fkey(c3) << 32) | (unsigned)(K_SZ - 2 - gk);
                if (k1 > k0) k0 = k1;
                if (k0 > best0) best0 = k0;
                if (k3 > k2) k2 = k3;
                if (k2 > best1) best1 = k2;
            }
#pragma unroll
            for (int m = 1; m <= 2; m <<= 1) {
                unsigned long long q0 = __shfl_xor_sync(0xffffffffu, best0, m);
                unsigned long long q1 = __shfl_xor_sync(0xffffffffu, best1, m);
                if (q0 > best0) best0 = q0;
                if (q1 > best1) best1 = q1;
            }
            if ((lane & 3) == 0) {
                atomicMax(&s_arg[r0], best0);
                atomicMax(&s_arg[r0 + 8], best1);
            }
        }
        __syncthreads();
        if (tid < 128) {
            g_tilemax[((size_t)(bt * 128 + tid) * H_SZ + h) * 32 + kt] = s_arg[tid];
            s_arg[tid] = 0ull;
        }
    }
}

// ---------------- rescue v2: tile-max guided exact argmax -------------------
#define MARGIN 8e-3f
__global__ void __launch_bounds__(256) rescue_kernel(const float* __restrict__ dist,
                                                     const float* __restrict__ cb,
                                                     float* __restrict__ zq,
                                                     float* __restrict__ idx_out) {
    int w = blockIdx.x * 8 + (threadIdx.x >> 5);  // (b*H + h)
    int lane = threadIdx.x & 31;
    int b = w >> 3, h = w & 7;

    // global approx max from 32 tile keys (one per lane)
    unsigned long long tkey = g_tilemax[(size_t)w * 32 + lane];
    unsigned long long gbest = tkey;
#pragma unroll
    for (int m = 16; m > 0; m >>= 1) {
        unsigned long long q = __shfl_xor_sync(0xffffffffu, gbest, m);
        if (q > gbest) gbest = q;
    }
    float thr = kinv((unsigned)(gbest >> 32)) - MARGIN;

    // this lane's slice of the normalized z row (4 floats)
    float4 zv = ((const float4*)(g_zn + (size_t)b * D_SZ + (size_t)h * HD))[lane];

    unsigned long long best = 0ull;
    unsigned tmask = __ballot_sync(0xffffffffu, kinv((unsigned)(tkey >> 32)) >= thr);
    while (tmask) {
        int t = __ffs(tmask) - 1;
        tmask &= tmask - 1;
        float4 dv = ((const float4*)(dist + (size_t)w * K_SZ + t * 128))[lane];
        float s4[4] = {1.0f - dv.x, 1.0f - dv.y, 1.0f - dv.z, 1.0f - dv.w};
#pragma unroll
        for (int j = 0; j < 4; j++) {
            unsigned pm = __ballot_sync(0xffffffffu, s4[j] >= thr);
            while (pm) {
                int src = __ffs(pm) - 1;
                pm &= pm - 1;
                int k = t * 128 + src * 4 + j;
                // cooperative exact fp32 dot (128 elems, 4/lane)
                float4 cv = ((const float4*)(g_cbn +
                             ((size_t)h * K_SZ + k) * HD))[lane];
                float p = fmaf(zv.x, cv.x,
                          fmaf(zv.y, cv.y, fmaf(zv.z, cv.z, zv.w * cv.w)));
#pragma unroll
                for (int m = 16; m > 0; m >>= 1)
                    p += __shfl_xor_sync(0xffffffffu, p, m);
                unsigned long long key =
                    ((unsigned long long)fkey(p) << 32) | (unsigned)(K_SZ - 1 - k);
                if (key > best) best = key;
            }
        }
    }
    int kbest = (K_SZ - 1) - (int)(best & 0xffffffffull);
    if (lane == 0) idx_out[w] = (float)kbest;
    float4 c = *(const float4*)(cb + ((size_t)h * K_SZ + kbest) * HD +
                                (size_t)lane * 4);
    *(float4*)(zq + (size_t)b * D_SZ + (size_t)h * HD + (size_t)lane * 4) = c;
}

// ---------------------------------------------------------------------------
extern "C" void kernel_launch(void* const* d_in, const int* in_sizes, int n_in,
                              void* d_out, int out_size) {
    const float* z  = (const float*)d_in[0];
    const float* cb = (const float*)d_in[1];
    float* out = (float*)d_out;

    float* zq   = out;
    float* idxo = out + (size_t)B_SZ * D_SZ;
    float* dist = out + (size_t)B_SZ * D_SZ + (size_t)B_SZ * H_SZ;

    cudaFuncSetAttribute(gemm_kernel,
                         cudaFuncAttributeMaxDynamicSharedMemorySize, SM_TOT);

    norm_z_kernel<<<B_SZ, 256>>>(z);
    norm_cb_kernel<<<H_SZ * K_SZ / 8, 256>>>(cb);

    dim3 grid(B_SZ / 128, H_SZ, 32 / KT_PER_CTA);
    gemm_kernel<<<grid, 256, SM_TOT>>>(dist);

    rescue_kernel<<<B_SZ * H_SZ / 8, 256>>>(dist, cb, zq, idxo);
}